// round 14
// baseline (speedup 1.0000x reference)
#include <cuda_runtime.h>
#include <cuda_bf16.h>
#include <cstdint>

#define Bsz   128
#define Tlen  1024
#define Isz   512
#define Hsz   512
#define NCTA  128
#define TPB   288      // 8 compute warps (4 kg x 2 ng) + 1 producer warp
#define PTPB  256
#define NKT   16
#define NSTG  8        // 2 stages per kg

// ---------------- device scratch ----------------
__device__ __align__(1024) char g_xs_hi[(size_t)Tlen * 2 * 8 * 8192];
__device__ __align__(1024) char g_xs_lo[(size_t)Tlen * 2 * 8 * 8192];
__device__ __align__(1024) char g_hs_hi[2 * 2 * 8 * 8192];
__device__ __align__(1024) char g_hs_lo[2 * 2 * 8 * 8192];
__device__ __nv_bfloat16 g_w_hi[(size_t)2048 * 1024];
__device__ __nv_bfloat16 g_w_lo[(size_t)2048 * 1024];
__device__ volatile unsigned g_flags[NCTA];

// ---------------- helpers ----------------
__device__ __forceinline__ uint32_t smem_u32(const void* p) {
    uint32_t a;
    asm("{ .reg .u64 t; cvta.to.shared.u64 t, %1; cvt.u32.u64 %0, t; }" : "=r"(a) : "l"(p));
    return a;
}
__device__ __forceinline__ void cpa16(uint32_t dst, const void* src) {
    asm volatile("cp.async.cg.shared.global [%0], [%1], 16;\n" :: "r"(dst), "l"(src));
}
#define CP_COMMIT()  asm volatile("cp.async.commit_group;\n")
#define CP_WAIT(n)   asm volatile("cp.async.wait_group %0;\n" :: "n"(n))

__device__ __forceinline__ void bulk_ld(uint32_t dst, const void* src, uint32_t bytes,
                                        uint32_t mbar) {
    asm volatile(
        "cp.async.bulk.shared::cluster.global.mbarrier::complete_tx::bytes [%0], [%1], %2, [%3];"
        :: "r"(dst), "l"(src), "r"(bytes), "r"(mbar) : "memory");
}
__device__ __forceinline__ void mbar_init(uint32_t m, uint32_t cnt) {
    asm volatile("mbarrier.init.shared.b64 [%0], %1;" :: "r"(m), "r"(cnt) : "memory");
}
__device__ __forceinline__ void mbar_expect(uint32_t m, uint32_t bytes) {
    asm volatile("mbarrier.arrive.expect_tx.shared.b64 _, [%0], %1;"
                 :: "r"(m), "r"(bytes) : "memory");
}
__device__ __forceinline__ void mbar_arrive(uint32_t m) {
    asm volatile("mbarrier.arrive.shared.b64 _, [%0];" :: "r"(m) : "memory");
}
__device__ __forceinline__ void mbar_wait(uint32_t m, uint32_t parity) {
    uint32_t done;
    asm volatile("{\n\t.reg .pred p;\n\t"
        "mbarrier.try_wait.parity.acquire.cta.shared::cta.b64 p, [%1], %2;\n\t"
        "selp.b32 %0, 1, 0, p;\n\t}"
        : "=r"(done) : "r"(m), "r"(parity) : "memory");
    if (!done) {
        asm volatile("{\n\t.reg .pred P1;\n\t"
            "WL_%=:\n\t"
            "mbarrier.try_wait.parity.acquire.cta.shared::cta.b64 P1, [%0], %1, 0x989680;\n\t"
            "@P1 bra.uni WD_%=;\n\t"
            "bra.uni WL_%=;\n\t"
            "WD_%=:\n\t}" :: "r"(m), "r"(parity) : "memory");
    }
}

#define LDSM4(r, a) \
    asm volatile("ldmatrix.sync.aligned.m8n8.x4.shared.b16 {%0,%1,%2,%3},[%4];" \
        : "=r"((r)[0]),"=r"((r)[1]),"=r"((r)[2]),"=r"((r)[3]) : "r"(a))
#define LDSM2(r, a) \
    asm volatile("ldmatrix.sync.aligned.m8n8.x2.shared.b16 {%0,%1},[%2];" \
        : "=r"((r)[0]),"=r"((r)[1]) : "r"(a))
#define MMA16816(d, a, b) \
    asm volatile("mma.sync.aligned.m16n8k16.row.col.f32.bf16.bf16.f32 " \
        "{%0,%1,%2,%3},{%4,%5,%6,%7},{%8,%9},{%0,%1,%2,%3};" \
        : "+f"((d)[0]),"+f"((d)[1]),"+f"((d)[2]),"+f"((d)[3]) \
        : "r"((a)[0]),"r"((a)[1]),"r"((a)[2]),"r"((a)[3]),"r"((b)[0]),"r"((b)[1]))

__device__ __forceinline__ float sigmoidf_(float x) { return 1.f / (1.f + expf(-x)); }

// ---------------- smem layout (bytes) ----------------
#define BS_OFF     0
#define MB_FULL    128          // 8 x 8B
#define MB_EMPTY   192          // 8 x 8B
#define WS_HI      1024
#define WS_LO      67072
#define WS_STRIDE  2064
#define RING_OFF   1024
#define A_BUF      16384
#define A_LOH      8192
#define ZP_OFF     132096
#define ZP_KG      9216         // 64 rows * 144B
#define ZP_ROW     144
#define SMEM_TOTAL 168960

// ---------------- prologue kernels ----------------
__global__ void init_kernel() {
    int idx = blockIdx.x * blockDim.x + threadIdx.x;
    int stride = gridDim.x * blockDim.x;
    int* hh = (int*)g_hs_hi;
    int* hl = (int*)g_hs_lo;
    for (int i = idx; i < (2 * 2 * 8 * 8192) / 4; i += stride) { hh[i] = 0; hl[i] = 0; }
    if (idx < NCTA) g_flags[idx] = 0u;
}

__global__ void prep_w(const float* __restrict__ Wk, const float* __restrict__ Rk) {
    __shared__ float tile[32][33];
    int gt = blockIdx.x * 32, kt = blockIdx.y * 32;
    int tid = threadIdx.x;
    for (int i = tid; i < 1024; i += PTPB) {
        int kk = i >> 5, gg = i & 31;
        int k = kt + kk, g = gt + gg;
        tile[kk][gg] = (k < 512) ? Wk[(size_t)k * 2048 + g]
                                 : Rk[(size_t)(k - 512) * 2048 + g];
    }
    __syncthreads();
    for (int i = tid; i < 1024; i += PTPB) {
        int gg = i >> 5, kk = i & 31;
        float v = tile[kk][gg];
        __nv_bfloat16 hi = __float2bfloat16(v);
        __nv_bfloat16 lo = __float2bfloat16(v - __bfloat162float(hi));
        size_t o = (size_t)(gt + gg) * 1024 + (size_t)(kt + kk);
        g_w_hi[o] = hi; g_w_lo[o] = lo;
    }
}

__global__ void prep_x(const float* __restrict__ x) {
    int t = blockIdx.x, b = blockIdx.y;
    int bg = b >> 6, r = b & 63;
    const float* src = x + ((size_t)b * Tlen + t) * Isz;
    size_t tbase = (((size_t)t * 2 + bg) * 8) * 8192;
    for (int k = threadIdx.x; k < Isz; k += blockDim.x) {
        float v = src[k];
        __nv_bfloat16 hi = __float2bfloat16(v);
        __nv_bfloat16 lo = __float2bfloat16(v - __bfloat162float(hi));
        int kt = k >> 6, kk = k & 63;
        size_t off = tbase + (size_t)kt * 8192 + r * 128 + (((kk * 2) ^ ((r & 7) << 4)));
        *(__nv_bfloat16*)(g_xs_hi + off) = hi;
        *(__nv_bfloat16*)(g_xs_lo + off) = lo;
    }
}

// ---------------- main persistent kernel ----------------
__global__ void __launch_bounds__(TPB, 1) lstm_mma(const float* __restrict__ bias,
                                                   float* __restrict__ out) {
    extern __shared__ char smem[];
    const uint32_t sbase = smem_u32(smem);
    float* bs = (float*)(smem + BS_OFF);

    const int tid = threadIdx.x, wid = tid >> 5, lid = tid & 31;
    const int cta = blockIdx.x;
    const int cg  = cta & 63;        // 8 h-cols
    const int bg  = cta >> 6;        // 64 batch rows
    const int kg  = wid >> 1;        // K-group: owns tiles kt ≡ kg (mod 4)
    const int ng  = wid & 1;         // N-group (16 n-cols)

    // ---- phase 0: weights into smem (transient) ----
    for (int i = tid; i < 32 * 128 * 2; i += TPB) {
        int half = i >= 32 * 128;
        int j = half ? i - 32 * 128 : i;
        int c = j >> 7, ch = j & 127;
        int g = (c & 3) * 512 + cg * 8 + (c >> 2);
        const __nv_bfloat16* src = (half ? g_w_lo : g_w_hi) + (size_t)g * 1024 + ch * 8;
        cpa16(sbase + (half ? WS_LO : WS_HI) + c * WS_STRIDE + ch * 16, src);
    }
    CP_COMMIT();
    if (tid < 32)
        bs[tid] = bias[(tid & 3) * 512 + cg * 8 + (tid >> 2)];
    if (tid == 0) {
        #pragma unroll
        for (int s = 0; s < NSTG; s++) {
            mbar_init(sbase + MB_FULL  + s * 8, 1);
            mbar_init(sbase + MB_EMPTY + s * 8, 2);
        }
    }
    CP_WAIT(0);
    __syncthreads();

    // ---- extract this warp's B fragments (tiles kt = kg + 4i), held forever ----
    uint32_t Bh[16][2][2], Bl[16][2][2];
    if (wid < 8) {
        #pragma unroll
        for (int kc = 0; kc < 16; kc++) {           // kc = i*4 + ks
            const uint32_t koff = kg * 128 + (kc >> 2) * 512 + (kc & 3) * 32;
            #pragma unroll
            for (int nt = 0; nt < 2; nt++) {
                uint32_t a = sbase + WS_HI
                           + (ng * 16 + nt * 8 + (lid & 7)) * WS_STRIDE
                           + ((lid >> 3) & 1) * 16 + koff;
                LDSM2(Bh[kc][nt], a);
                LDSM2(Bl[kc][nt], a + (WS_LO - WS_HI));
            }
        }
    }
    __syncthreads();   // ws region dead; ring/zpart overlay it

    // stage map (R8): stage s serves x tile x_kt(s) = (s>>1) + (s&1)*4
    // and h tile x_kt(s)+8, each once per step.
    const int x_kt  = (lid >> 1) + (lid & 1) * 4;          // valid for lid<8
    const int h_src = bg * 64 + x_kt * 8;                  // 8 source CTAs of h tile

    // ---- producer prime: lane s loads its x tile of step 0 ----
    if (wid == 8 && lid < 8) {
        const int s = lid;
        mbar_wait(sbase + MB_EMPTY + s * 8, 1);            // fresh: passes
        size_t o = (((size_t)0 * 2 + bg) * 8 + x_kt) * 8192;
        const uint32_t abuf = sbase + RING_OFF + s * A_BUF;
        mbar_expect(sbase + MB_FULL + s * 8, 16384);
        bulk_ld(abuf,         g_xs_hi + o, 8192, sbase + MB_FULL + s * 8);
        bulk_ld(abuf + A_LOH, g_xs_lo + o, 8192, sbase + MB_FULL + s * 8);
    }

    // compute-warp A addressing
    const uint32_t a_row   = (lid & 15) * 128;
    const uint32_t a_cmask = (lid & 7) << 4;
    const uint32_t a_chi   = (lid >> 4) * 16;

    float creg[2] = {0.f, 0.f};

    for (int t = 0; t < Tlen; t++) {
        if (wid == 8) {
            // ------------- producer warp: 8 parallel lanes -------------
            if (lid < 8) {
                const int s = lid;
                const uint32_t abuf  = sbase + RING_OFF + s * A_BUF;
                const uint32_t fullb = sbase + MB_FULL  + s * 8;
                const uint32_t empb  = sbase + MB_EMPTY + s * 8;
                // fine-grained gate: this lane's h tile needs only its 8 sources
                if (t > 0) {
                    unsigned tgt = (unsigned)t;
                    bool ok;
                    do {
                        ok = true;
                        #pragma unroll
                        for (int j = 0; j < 8; j++)
                            ok &= (g_flags[h_src + j] >= tgt);
                    } while (!ok);
                    __threadfence();
                }
                // h tile (fill 2t+1): wait empty completion #2t+1 → parity 0
                mbar_wait(empb, 0);
                {
                    size_t o = (((size_t)(t & 1) * 2 + bg) * 8 + x_kt) * 8192;
                    mbar_expect(fullb, 16384);
                    bulk_ld(abuf,         g_hs_hi + o, 8192, fullb);
                    bulk_ld(abuf + A_LOH, g_hs_lo + o, 8192, fullb);
                }
                // x tile of t+1 (fill 2t+2): wait empty completion #2t+2 → parity 1
                if (t + 1 < Tlen) {
                    mbar_wait(empb, 1);
                    size_t o = (((size_t)(t + 1) * 2 + bg) * 8 + x_kt) * 8192;
                    mbar_expect(fullb, 16384);
                    bulk_ld(abuf,         g_xs_hi + o, 8192, fullb);
                    bulk_ld(abuf + A_LOH, g_xs_lo + o, 8192, fullb);
                }
            }
        } else {
            // ------------- compute warps: tiles kt = kg + 4i -------------
            float acc[4][2][4];
            #pragma unroll
            for (int mt = 0; mt < 4; mt++)
                #pragma unroll
                for (int nt = 0; nt < 2; nt++)
                    #pragma unroll
                    for (int j = 0; j < 4; j++) acc[mt][nt][j] = 0.f;

            #pragma unroll
            for (int i = 0; i < 4; i++) {
                const int s = (kg << 1) | (i & 1);
                mbar_wait(sbase + MB_FULL + s * 8, i >> 1);   // x: parity 0, h: parity 1

                const uint32_t abuf = sbase + RING_OFF + s * A_BUF;
                #pragma unroll
                for (int ks = 0; ks < 4; ks++) {
                    const uint32_t col = ((uint32_t)(ks * 32) + a_chi) ^ a_cmask;
                    #pragma unroll
                    for (int mt = 0; mt < 4; mt++) {
                        uint32_t ah[4], al[4];
                        LDSM4(ah, abuf + mt * 2048 + a_row + col);
                        LDSM4(al, abuf + A_LOH + mt * 2048 + a_row + col);
                        #pragma unroll
                        for (int nt = 0; nt < 2; nt++) {
                            MMA16816(acc[mt][nt], ah, Bh[i * 4 + ks][nt]);
                            MMA16816(acc[mt][nt], ah, Bl[i * 4 + ks][nt]);
                            MMA16816(acc[mt][nt], al, Bh[i * 4 + ks][nt]);
                        }
                    }
                }
                if (lid == 0) mbar_arrive(sbase + MB_EMPTY + s * 8);
            }

            // store fp32 partials to zpart[kg]
            #pragma unroll
            for (int mt = 0; mt < 4; mt++) {
                #pragma unroll
                for (int nt = 0; nt < 2; nt++) {
                    const int r0 = mt * 16 + (lid >> 2);
                    const int c0 = ng * 16 + nt * 8 + (lid & 3) * 2;
                    char* base = smem + ZP_OFF + kg * ZP_KG + c0 * 4;
                    *(float2*)(base + r0 * ZP_ROW) =
                        make_float2(acc[mt][nt][0], acc[mt][nt][1]);
                    *(float2*)(base + (r0 + 8) * ZP_ROW) =
                        make_float2(acc[mt][nt][2], acc[mt][nt][3]);
                }
            }
        }

        __syncthreads();    // partials visible

        // ---- reduce across K-groups + gates (compute threads, 2 elems each) ----
        if (wid < 8) {
            const int par2 = (t + 1) & 1;
            #pragma unroll
            for (int e = 0; e < 2; e++) {
                const int el = tid * 2 + e;          // 0..511
                const int b  = el >> 3;              // 0..63
                const int hc = el & 7;               // 0..7
                float4 z = make_float4(0.f, 0.f, 0.f, 0.f);
                #pragma unroll
                for (int k4 = 0; k4 < 4; k4++) {
                    float4 p = *(const float4*)(smem + ZP_OFF + k4 * ZP_KG
                                                + b * ZP_ROW + hc * 16);
                    z.x += p.x; z.y += p.y; z.z += p.z; z.w += p.w;
                }
                float zi = z.x + bs[hc * 4 + 0];
                float zf = z.y + bs[hc * 4 + 1];
                float zg = z.z + bs[hc * 4 + 2];
                float zo = z.w + bs[hc * 4 + 3];
                float ii = sigmoidf_(zi);
                float ff = sigmoidf_(zf);
                float gg = tanhf(zg);
                float oo = sigmoidf_(zo);
                float cn = tanhf(ff * creg[e] + ii * gg);
                float hn = oo * cn;
                creg[e] = cn;

                const int b_glob = bg * 64 + b;
                const int hcol   = cg * 8 + hc;
                out[(size_t)b_glob * (Tlen * Hsz) + (size_t)t * Hsz + hcol] = hn;

                __nv_bfloat16 hh = __float2bfloat16(hn);
                size_t off = (((size_t)par2 * 2 + bg) * 8 + (hcol >> 6)) * 8192
                           + b * 128 + ((((hcol & 63) * 2) ^ ((b & 7) << 4)));
                *(__nv_bfloat16*)(g_hs_hi + off) = hh;
                *(__nv_bfloat16*)(g_hs_lo + off) =
                    __float2bfloat16(hn - __bfloat162float(hh));
            }
            __threadfence();
        }

        __syncthreads();    // h published

        if (wid == 8 && lid == 0 && t < Tlen - 1)
            g_flags[cta] = (unsigned)(t + 1);
    }
}

// ---------------- launch ----------------
extern "C" void kernel_launch(void* const* d_in, const int* in_sizes, int n_in,
                              void* d_out, int out_size) {
    const float* x    = (const float*)d_in[0];
    const float* Wk   = (const float*)d_in[1];
    const float* Rk   = (const float*)d_in[2];
    const float* bias = (const float*)d_in[3];
    float* out = (float*)d_out;

    cudaFuncSetAttribute(lstm_mma, cudaFuncAttributeMaxDynamicSharedMemorySize, SMEM_TOTAL);

    init_kernel<<<64, PTPB>>>();
    prep_w<<<dim3(64, 32), PTPB>>>(Wk, Rk);
    prep_x<<<dim3(Tlen, Bsz), 128>>>(x);
    lstm_mma<<<NCTA, TPB, SMEM_TOTAL>>>(bias, out);
}

// round 15
// speedup vs baseline: 1.4124x; 1.4124x over previous
#include <cuda_runtime.h>
#include <cuda_bf16.h>
#include <cstdint>

#define Bsz   128
#define Tlen  1024
#define Isz   512
#define Hsz   512
#define NCTA  128
#define TPB   288      // 8 compute warps (4 kg x 2 ng) + 1 producer warp
#define PTPB  256
#define NSTG  8

// ---------------- device scratch ----------------
__device__ __align__(1024) char g_xs_hi[(size_t)Tlen * 2 * 8 * 8192];
__device__ __align__(1024) char g_xs_lo[(size_t)Tlen * 2 * 8 * 8192];
__device__ __align__(1024) char g_zx[(size_t)Tlen * NCTA * 8192];     // 1 GiB fp32 z_x
__device__ __align__(1024) char g_hb_hi[2 * NCTA * 1024];             // h blocks [par][cta][64][8]bf16
__device__ __align__(1024) char g_hb_lo[2 * NCTA * 1024];
__device__ __nv_bfloat16 g_w_hi[(size_t)2048 * 1024];
__device__ __nv_bfloat16 g_w_lo[(size_t)2048 * 1024];
__device__ volatile unsigned g_flags[NCTA];
__device__ volatile unsigned g_release;

// ---------------- helpers ----------------
__device__ __forceinline__ uint32_t smem_u32(const void* p) {
    uint32_t a;
    asm("{ .reg .u64 t; cvta.to.shared.u64 t, %1; cvt.u32.u64 %0, t; }" : "=r"(a) : "l"(p));
    return a;
}
__device__ __forceinline__ void cpa16(uint32_t dst, const void* src) {
    asm volatile("cp.async.cg.shared.global [%0], [%1], 16;\n" :: "r"(dst), "l"(src));
}
#define CP_COMMIT()  asm volatile("cp.async.commit_group;\n")
#define CP_WAIT(n)   asm volatile("cp.async.wait_group %0;\n" :: "n"(n))

__device__ __forceinline__ void bulk_ld(uint32_t dst, const void* src, uint32_t bytes,
                                        uint32_t mbar) {
    asm volatile(
        "cp.async.bulk.shared::cluster.global.mbarrier::complete_tx::bytes [%0], [%1], %2, [%3];"
        :: "r"(dst), "l"(src), "r"(bytes), "r"(mbar) : "memory");
}
__device__ __forceinline__ void mbar_init(uint32_t m, uint32_t cnt) {
    asm volatile("mbarrier.init.shared.b64 [%0], %1;" :: "r"(m), "r"(cnt) : "memory");
}
__device__ __forceinline__ void mbar_expect(uint32_t m, uint32_t bytes) {
    asm volatile("mbarrier.arrive.expect_tx.shared.b64 _, [%0], %1;"
                 :: "r"(m), "r"(bytes) : "memory");
}
__device__ __forceinline__ void mbar_arrive(uint32_t m) {
    asm volatile("mbarrier.arrive.shared.b64 _, [%0];" :: "r"(m) : "memory");
}
__device__ __forceinline__ void mbar_wait(uint32_t m, uint32_t parity) {
    uint32_t done;
    asm volatile("{\n\t.reg .pred p;\n\t"
        "mbarrier.try_wait.parity.acquire.cta.shared::cta.b64 p, [%1], %2;\n\t"
        "selp.b32 %0, 1, 0, p;\n\t}"
        : "=r"(done) : "r"(m), "r"(parity) : "memory");
    if (!done) {
        asm volatile("{\n\t.reg .pred P1;\n\t"
            "WL_%=:\n\t"
            "mbarrier.try_wait.parity.acquire.cta.shared::cta.b64 P1, [%0], %1, 0x989680;\n\t"
            "@P1 bra.uni WD_%=;\n\t"
            "bra.uni WL_%=;\n\t"
            "WD_%=:\n\t}" :: "r"(m), "r"(parity) : "memory");
    }
}

#define LDSM4(r, a) \
    asm volatile("ldmatrix.sync.aligned.m8n8.x4.shared.b16 {%0,%1,%2,%3},[%4];" \
        : "=r"((r)[0]),"=r"((r)[1]),"=r"((r)[2]),"=r"((r)[3]) : "r"(a))
#define LDSM2(r, a) \
    asm volatile("ldmatrix.sync.aligned.m8n8.x2.shared.b16 {%0,%1},[%2];" \
        : "=r"((r)[0]),"=r"((r)[1]) : "r"(a))
#define MMA16816(d, a, b) \
    asm volatile("mma.sync.aligned.m16n8k16.row.col.f32.bf16.bf16.f32 " \
        "{%0,%1,%2,%3},{%4,%5,%6,%7},{%8,%9},{%0,%1,%2,%3};" \
        : "+f"((d)[0]),"+f"((d)[1]),"+f"((d)[2]),"+f"((d)[3]) \
        : "r"((a)[0]),"r"((a)[1]),"r"((a)[2]),"r"((a)[3]),"r"((b)[0]),"r"((b)[1]))

__device__ __forceinline__ float sigmoidf_(float x) { return 1.f / (1.f + expf(-x)); }

// ---------------- smem layout (bytes) ----------------
#define BS_OFF     0
#define MB_FULL    128          // 8 x 8B
#define MB_EMPTY   192          // 8 x 8B
#define MB_ZXF     256          // 2 x 8B
#define WS_HI      1024
#define WS_STRIDE  1040         // 512 k bf16 + 8 pad
#define WS_LO      34304        // 1024 + 32*1040
#define RING_OFF   1024
#define A_BUF      16384
#define A_LOH      8192
#define ZP_OFF     132096       // RING_OFF + 8*16384
#define ZP_KG      9216
#define ZP_ROW     144
#define ZX_OFF     168960       // ZP_OFF + 4*9216
#define SMEM_ZX    168960       // zx_gemm: ring + 4 zpart
#define SMEM_MAIN  185344       // + 2 zx slots (8192 each)

// ---------------- prologue kernels ----------------
__global__ void init_kernel() {
    int idx = blockIdx.x * blockDim.x + threadIdx.x;
    int stride = gridDim.x * blockDim.x;
    int* hh = (int*)g_hb_hi;
    int* hl = (int*)g_hb_lo;
    for (int i = idx; i < (2 * NCTA * 1024) / 4; i += stride) { hh[i] = 0; hl[i] = 0; }
    if (idx < NCTA) g_flags[idx] = 0u;
    if (idx == 0)   g_release   = 0u;
}

__global__ void prep_w(const float* __restrict__ Wk, const float* __restrict__ Rk) {
    __shared__ float tile[32][33];
    int gt = blockIdx.x * 32, kt = blockIdx.y * 32;
    int tid = threadIdx.x;
    for (int i = tid; i < 1024; i += PTPB) {
        int kk = i >> 5, gg = i & 31;
        int k = kt + kk, g = gt + gg;
        tile[kk][gg] = (k < 512) ? Wk[(size_t)k * 2048 + g]
                                 : Rk[(size_t)(k - 512) * 2048 + g];
    }
    __syncthreads();
    for (int i = tid; i < 1024; i += PTPB) {
        int gg = i >> 5, kk = i & 31;
        float v = tile[kk][gg];
        __nv_bfloat16 hi = __float2bfloat16(v);
        __nv_bfloat16 lo = __float2bfloat16(v - __bfloat162float(hi));
        size_t o = (size_t)(gt + gg) * 1024 + (size_t)(kt + kk);
        g_w_hi[o] = hi; g_w_lo[o] = lo;
    }
}

__global__ void prep_x(const float* __restrict__ x) {
    int t = blockIdx.x, b = blockIdx.y;
    int bg = b >> 6, r = b & 63;
    const float* src = x + ((size_t)b * Tlen + t) * Isz;
    size_t tbase = (((size_t)t * 2 + bg) * 8) * 8192;
    for (int k = threadIdx.x; k < Isz; k += blockDim.x) {
        float v = src[k];
        __nv_bfloat16 hi = __float2bfloat16(v);
        __nv_bfloat16 lo = __float2bfloat16(v - __bfloat162float(hi));
        int kt = k >> 6, kk = k & 63;
        size_t off = tbase + (size_t)kt * 8192 + r * 128 + (((kk * 2) ^ ((r & 7) << 4)));
        *(__nv_bfloat16*)(g_xs_hi + off) = hi;
        *(__nv_bfloat16*)(g_xs_lo + off) = lo;
    }
}

// ---------------- prologue GEMM: z_x = x@W + bias ----------------
__global__ void __launch_bounds__(TPB, 1) zx_gemm(const float* __restrict__ bias) {
    extern __shared__ char smem[];
    const uint32_t sbase = smem_u32(smem);
    float* bs = (float*)(smem + BS_OFF);

    const int tid = threadIdx.x, wid = tid >> 5, lid = tid & 31;
    const int cta = blockIdx.x;
    const int cg  = cta & 63;
    const int bg  = cta >> 6;
    const int kg  = wid >> 1;
    const int ng  = wid & 1;

    // weights (x part, k 0..511) into smem
    for (int i = tid; i < 4096; i += TPB) {
        int half = i >= 2048;
        int j = half ? i - 2048 : i;
        int c = j >> 6, ch = j & 63;
        int g = (c & 3) * 512 + cg * 8 + (c >> 2);
        const __nv_bfloat16* src = (half ? g_w_lo : g_w_hi) + (size_t)g * 1024 + ch * 8;
        cpa16(sbase + (half ? WS_LO : WS_HI) + c * WS_STRIDE + ch * 16, src);
    }
    CP_COMMIT();
    if (tid < 32)
        bs[tid] = bias[(tid & 3) * 512 + cg * 8 + (tid >> 2)];
    if (tid == 0) {
        #pragma unroll
        for (int s = 0; s < NSTG; s++) {
            mbar_init(sbase + MB_FULL  + s * 8, 1);
            mbar_init(sbase + MB_EMPTY + s * 8, 2);
        }
    }
    CP_WAIT(0);
    __syncthreads();

    uint32_t Bh[2][4][2][2], Bl[2][4][2][2];
    if (wid < 8) {
        #pragma unroll
        for (int jj = 0; jj < 2; jj++) {
            const uint32_t koff = (kg + jj * 4) * 128;
            #pragma unroll
            for (int ks = 0; ks < 4; ks++)
                #pragma unroll
                for (int nt = 0; nt < 2; nt++) {
                    uint32_t a = sbase + WS_HI
                               + (ng * 16 + nt * 8 + (lid & 7)) * WS_STRIDE
                               + ((lid >> 3) & 1) * 16 + koff + ks * 32;
                    LDSM2(Bh[jj][ks][nt], a);
                    LDSM2(Bl[jj][ks][nt], a + (WS_LO - WS_HI));
                }
        }
    }
    __syncthreads();   // ws dead; ring/zpart overlay

    const int x_kt_p = (lid >> 1) + (lid & 1) * 4;   // producer lane's tile (lid<8)

    // prime: fill all 8 stages for t=0 (empty fresh: parity 1 passes)
    if (wid == 8 && lid < 8) {
        const int s = lid;
        mbar_wait(sbase + MB_EMPTY + s * 8, 1);
        size_t o = (((size_t)0 * 2 + bg) * 8 + x_kt_p) * 8192;
        const uint32_t abuf = sbase + RING_OFF + s * A_BUF;
        mbar_expect(sbase + MB_FULL + s * 8, 16384);
        bulk_ld(abuf,         g_xs_hi + o, 8192, sbase + MB_FULL + s * 8);
        bulk_ld(abuf + A_LOH, g_xs_lo + o, 8192, sbase + MB_FULL + s * 8);
    }

    const uint32_t a_row   = (lid & 15) * 128;
    const uint32_t a_cmask = (lid & 7) << 4;
    const uint32_t a_chi   = (lid >> 4) * 16;

    for (int t = 0; t < Tlen; t++) {
        if (wid == 8) {
            if (lid < 8 && t + 1 < Tlen) {
                const int s = lid;
                mbar_wait(sbase + MB_EMPTY + s * 8, t & 1);   // completion #(t+1)
                size_t o = (((size_t)(t + 1) * 2 + bg) * 8 + x_kt_p) * 8192;
                const uint32_t abuf = sbase + RING_OFF + s * A_BUF;
                mbar_expect(sbase + MB_FULL + s * 8, 16384);
                bulk_ld(abuf,         g_xs_hi + o, 8192, sbase + MB_FULL + s * 8);
                bulk_ld(abuf + A_LOH, g_xs_lo + o, 8192, sbase + MB_FULL + s * 8);
            }
        } else {
            float acc[4][2][4];
            #pragma unroll
            for (int mt = 0; mt < 4; mt++)
                #pragma unroll
                for (int nt = 0; nt < 2; nt++)
                    #pragma unroll
                    for (int j = 0; j < 4; j++) acc[mt][nt][j] = 0.f;

            #pragma unroll
            for (int i = 0; i < 2; i++) {
                const int s = kg * 2 + i;
                mbar_wait(sbase + MB_FULL + s * 8, t & 1);
                const uint32_t abuf = sbase + RING_OFF + s * A_BUF;
                #pragma unroll
                for (int ks = 0; ks < 4; ks++) {
                    const uint32_t col = ((uint32_t)(ks * 32) + a_chi) ^ a_cmask;
                    #pragma unroll
                    for (int mt = 0; mt < 4; mt++) {
                        uint32_t ah[4], al[4];
                        LDSM4(ah, abuf + mt * 2048 + a_row + col);
                        LDSM4(al, abuf + A_LOH + mt * 2048 + a_row + col);
                        #pragma unroll
                        for (int nt = 0; nt < 2; nt++) {
                            MMA16816(acc[mt][nt], ah, Bh[i][ks][nt]);
                            MMA16816(acc[mt][nt], ah, Bl[i][ks][nt]);
                            MMA16816(acc[mt][nt], al, Bh[i][ks][nt]);
                        }
                    }
                }
                if (lid == 0) mbar_arrive(sbase + MB_EMPTY + s * 8);
            }

            #pragma unroll
            for (int mt = 0; mt < 4; mt++) {
                #pragma unroll
                for (int nt = 0; nt < 2; nt++) {
                    const int r0 = mt * 16 + (lid >> 2);
                    const int c0 = ng * 16 + nt * 8 + (lid & 3) * 2;
                    char* base = smem + ZP_OFF + kg * ZP_KG + c0 * 4;
                    *(float2*)(base + r0 * ZP_ROW) =
                        make_float2(acc[mt][nt][0], acc[mt][nt][1]);
                    *(float2*)(base + (r0 + 8) * ZP_ROW) =
                        make_float2(acc[mt][nt][2], acc[mt][nt][3]);
                }
            }
        }

        __syncthreads();

        if (wid < 8) {
            float4* dst = (float4*)(g_zx + ((size_t)t * NCTA + cta) * 8192);
            #pragma unroll
            for (int e = 0; e < 2; e++) {
                const int el = tid * 2 + e;
                const int hc = el & 7;
                float4 z = make_float4(0.f, 0.f, 0.f, 0.f);
                #pragma unroll
                for (int k4 = 0; k4 < 4; k4++) {
                    float4 p = *(const float4*)(smem + ZP_OFF + k4 * ZP_KG
                                                + (el >> 3) * ZP_ROW + hc * 16);
                    z.x += p.x; z.y += p.y; z.z += p.z; z.w += p.w;
                }
                z.x += bs[hc * 4 + 0];
                z.y += bs[hc * 4 + 1];
                z.z += bs[hc * 4 + 2];
                z.w += bs[hc * 4 + 3];
                dst[el] = z;
            }
        }

        __syncthreads();
    }
}

// ---------------- main recurrent kernel: z = z_x + h@R ----------------
__global__ void __launch_bounds__(TPB, 1) lstm_h(float* __restrict__ out) {
    extern __shared__ char smem[];
    const uint32_t sbase = smem_u32(smem);

    const int tid = threadIdx.x, wid = tid >> 5, lid = tid & 31;
    const int cta = blockIdx.x;
    const int cg  = cta & 63;
    const int bg  = cta >> 6;
    const int kg  = wid >> 1;
    const int ng  = wid & 1;

    // weights (R part, k 512..1023) into smem
    for (int i = tid; i < 4096; i += TPB) {
        int half = i >= 2048;
        int j = half ? i - 2048 : i;
        int c = j >> 6, ch = j & 63;
        int g = (c & 3) * 512 + cg * 8 + (c >> 2);
        const __nv_bfloat16* src = (half ? g_w_lo : g_w_hi)
                                   + (size_t)g * 1024 + 512 + ch * 8;
        cpa16(sbase + (half ? WS_LO : WS_HI) + c * WS_STRIDE + ch * 16, src);
    }
    CP_COMMIT();
    if (tid == 0) {
        #pragma unroll
        for (int s = 0; s < NSTG; s++) {
            mbar_init(sbase + MB_FULL  + s * 8, 1);
            mbar_init(sbase + MB_EMPTY + s * 8, 2);
        }
        mbar_init(sbase + MB_ZXF,     1);
        mbar_init(sbase + MB_ZXF + 8, 1);
    }
    CP_WAIT(0);
    __syncthreads();

    uint32_t Bh[2][4][2][2], Bl[2][4][2][2];
    if (wid < 8) {
        #pragma unroll
        for (int jj = 0; jj < 2; jj++) {
            const uint32_t koff = (kg + jj * 4) * 128;
            #pragma unroll
            for (int ks = 0; ks < 4; ks++)
                #pragma unroll
                for (int nt = 0; nt < 2; nt++) {
                    uint32_t a = sbase + WS_HI
                               + (ng * 16 + nt * 8 + (lid & 7)) * WS_STRIDE
                               + ((lid >> 3) & 1) * 16 + koff + ks * 32;
                    LDSM2(Bh[jj][ks][nt], a);
                    LDSM2(Bl[jj][ks][nt], a + (WS_LO - WS_HI));
                }
        }
    }
    __syncthreads();   // ws dead; ring/zpart/zx overlay

    // prime zx slots 0,1 (steps 0,1)
    if (wid == 8 && lid == 30) {
        mbar_expect(sbase + MB_ZXF, 8192);
        bulk_ld(sbase + ZX_OFF, g_zx + ((size_t)0 * NCTA + cta) * 8192, 8192,
                sbase + MB_ZXF);
    }
    if (wid == 8 && lid == 31) {
        mbar_expect(sbase + MB_ZXF + 8, 8192);
        bulk_ld(sbase + ZX_OFF + 8192, g_zx + ((size_t)1 * NCTA + cta) * 8192, 8192,
                sbase + MB_ZXF + 8);
    }

    // A-fragment addressing (h layout: [j:8][64 rows][16B], no swizzle)
    const uint32_t a_part = (uint32_t)((lid >> 4) * 1024 + (lid & 15) * 16);

    float creg[2] = {0.f, 0.f};

    for (int t = 0; t < Tlen; t++) {
        if (wid == 8) {
            // hierarchical global barrier
            if (t > 0) {
                if (cta == 0) {
                    bool ok;
                    do {
                        ok = (g_flags[lid]      >= (unsigned)t)
                          && (g_flags[lid + 32] >= (unsigned)t)
                          && (g_flags[lid + 64] >= (unsigned)t)
                          && (g_flags[lid + 96] >= (unsigned)t);
                    } while (!__all_sync(0xffffffffu, ok));
                    if (lid == 0) { __threadfence(); g_release = (unsigned)t; }
                } else if (lid == 0) {
                    while (g_release < (unsigned)t) { }
                }
                __syncwarp();
                __threadfence();
            }
            // gather h tiles: 4 lanes per stage
            {
                const int s = lid >> 2, q = lid & 3;
                const int kt_h = (s >> 1) + (s & 1) * 4;
                const uint32_t fullb = sbase + MB_FULL  + s * 8;
                const uint32_t empb  = sbase + MB_EMPTY + s * 8;
                const uint32_t abuf  = sbase + RING_OFF + s * A_BUF;
                mbar_wait(empb, (t + 1) & 1);    // completion #t (t=0: fresh-pass)
                if (q == 0) mbar_expect(fullb, 16384);
                const int par = t & 1;
                #pragma unroll
                for (int w = 0; w < 2; w++) {
                    const int j = q * 2 + w;
                    const int src_cta = bg * 64 + kt_h * 8 + j;
                    bulk_ld(abuf + j * 1024,
                            g_hb_hi + ((size_t)par * NCTA + src_cta) * 1024, 1024, fullb);
                    bulk_ld(abuf + A_LOH + j * 1024,
                            g_hb_lo + ((size_t)par * NCTA + src_cta) * 1024, 1024, fullb);
                }
            }
        } else {
            float acc[4][2][4];
            #pragma unroll
            for (int mt = 0; mt < 4; mt++)
                #pragma unroll
                for (int nt = 0; nt < 2; nt++)
                    #pragma unroll
                    for (int j = 0; j < 4; j++) acc[mt][nt][j] = 0.f;

            #pragma unroll
            for (int i = 0; i < 2; i++) {
                const int s = kg * 2 + i;
                mbar_wait(sbase + MB_FULL + s * 8, t & 1);
                const uint32_t abuf = sbase + RING_OFF + s * A_BUF;
                #pragma unroll
                for (int ks = 0; ks < 4; ks++) {
                    #pragma unroll
                    for (int mt = 0; mt < 4; mt++) {
                        uint32_t ah[4], al[4];
                        const uint32_t ao = abuf + ks * 2048 + mt * 256 + a_part;
                        LDSM4(ah, ao);
                        LDSM4(al, ao + A_LOH);
                        #pragma unroll
                        for (int nt = 0; nt < 2; nt++) {
                            MMA16816(acc[mt][nt], ah, Bh[i][ks][nt]);
                            MMA16816(acc[mt][nt], ah, Bl[i][ks][nt]);
                            MMA16816(acc[mt][nt], al, Bh[i][ks][nt]);
                        }
                    }
                }
                if (lid == 0) mbar_arrive(sbase + MB_EMPTY + s * 8);
            }

            #pragma unroll
            for (int mt = 0; mt < 4; mt++) {
                #pragma unroll
                for (int nt = 0; nt < 2; nt++) {
                    const int r0 = mt * 16 + (lid >> 2);
                    const int c0 = ng * 16 + nt * 8 + (lid & 3) * 2;
                    char* base = smem + ZP_OFF + kg * ZP_KG + c0 * 4;
                    *(float2*)(base + r0 * ZP_ROW) =
                        make_float2(acc[mt][nt][0], acc[mt][nt][1]);
                    *(float2*)(base + (r0 + 8) * ZP_ROW) =
                        make_float2(acc[mt][nt][2], acc[mt][nt][3]);
                }
            }
        }

        __syncthreads();    // partials visible

        if (wid < 8) {
            mbar_wait(sbase + MB_ZXF + (t & 1) * 8, (t >> 1) & 1);
            const int par2 = (t + 1) & 1;
            const int el0 = tid * 2;
            const int b   = el0 >> 3;
            const int hc0 = el0 & 7;
            float hv[2];
            #pragma unroll
            for (int e = 0; e < 2; e++) {
                const int el = el0 + e;
                const int hc = hc0 + e;
                float4 z = *(const float4*)(smem + ZX_OFF + (t & 1) * 8192 + el * 16);
                #pragma unroll
                for (int k4 = 0; k4 < 4; k4++) {
                    float4 p = *(const float4*)(smem + ZP_OFF + k4 * ZP_KG
                                                + b * ZP_ROW + hc * 16);
                    z.x += p.x; z.y += p.y; z.z += p.z; z.w += p.w;
                }
                float ii = sigmoidf_(z.x);
                float ff = sigmoidf_(z.y);
                float gg = tanhf(z.z);
                float oo = sigmoidf_(z.w);
                float cn = tanhf(ff * creg[e] + ii * gg);
                float hn = oo * cn;
                creg[e] = cn;
                hv[e] = hn;
                out[(size_t)(bg * 64 + b) * (Tlen * Hsz) + (size_t)t * Hsz
                    + cg * 8 + hc] = hn;
            }
            // coalesced h block store (hi/lo bf16x2)
            __nv_bfloat16 h0 = __float2bfloat16(hv[0]);
            __nv_bfloat16 h1 = __float2bfloat16(hv[1]);
            __nv_bfloat162 hi2; hi2.x = h0; hi2.y = h1;
            __nv_bfloat162 lo2;
            lo2.x = __float2bfloat16(hv[0] - __bfloat162float(h0));
            lo2.y = __float2bfloat16(hv[1] - __bfloat162float(h1));
            size_t boff = ((size_t)par2 * NCTA + cta) * 1024 + b * 16 + hc0 * 2;
            *(__nv_bfloat162*)(g_hb_hi + boff) = hi2;
            *(__nv_bfloat162*)(g_hb_lo + boff) = lo2;
            __threadfence();
        }

        __syncthreads();    // h published

        if (wid == 8) {
            if (lid == 0 && t < Tlen - 1)
                g_flags[cta] = (unsigned)(t + 1);
            if (lid == 31 && t + 2 < Tlen) {
                mbar_expect(sbase + MB_ZXF + (t & 1) * 8, 8192);
                bulk_ld(sbase + ZX_OFF + (t & 1) * 8192,
                        g_zx + ((size_t)(t + 2) * NCTA + cta) * 8192, 8192,
                        sbase + MB_ZXF + (t & 1) * 8);
            }
        }
    }
}

// ---------------- launch ----------------
extern "C" void kernel_launch(void* const* d_in, const int* in_sizes, int n_in,
                              void* d_out, int out_size) {
    const float* x    = (const float*)d_in[0];
    const float* Wk   = (const float*)d_in[1];
    const float* Rk   = (const float*)d_in[2];
    const float* bias = (const float*)d_in[3];
    float* out = (float*)d_out;

    cudaFuncSetAttribute(zx_gemm, cudaFuncAttributeMaxDynamicSharedMemorySize, SMEM_ZX);
    cudaFuncSetAttribute(lstm_h,  cudaFuncAttributeMaxDynamicSharedMemorySize, SMEM_MAIN);

    init_kernel<<<64, PTPB>>>();
    prep_w<<<dim3(64, 32), PTPB>>>(Wk, Rk);
    prep_x<<<dim3(Tlen, Bsz), 128>>>(x);
    zx_gemm<<<NCTA, TPB, SMEM_ZX>>>(bias);
    lstm_h<<<NCTA, TPB, SMEM_MAIN>>>(out);
}

// round 16
// speedup vs baseline: 1.7629x; 1.2481x over previous
#include <cuda_runtime.h>
#include <cuda_bf16.h>
#include <cstdint>

#define Bsz   128
#define Tlen  1024
#define Isz   512
#define Hsz   512
#define NCTA  128
#define TPB   288
#define PTPB  256
#define NSTG  8

// ---------------- device scratch ----------------
__device__ __align__(1024) char g_xs_hi[(size_t)Tlen * 2 * 8 * 8192];
__device__ __align__(1024) char g_xs_lo[(size_t)Tlen * 2 * 8 * 8192];
__device__ __align__(1024) char g_zx[(size_t)Tlen * NCTA * 8192];     // fp32 z_x
__device__ __align__(1024) char g_hb_hi[2 * NCTA * 1024];             // [par][cta][64][8]bf16
__device__ __align__(1024) char g_hb_lo[2 * NCTA * 1024];
__device__ __nv_bfloat16 g_w_hi[(size_t)2048 * 1024];
__device__ __nv_bfloat16 g_w_lo[(size_t)2048 * 1024];
__device__ volatile unsigned g_flags[NCTA];
__device__ volatile unsigned g_rel[2];

// ---------------- helpers ----------------
__device__ __forceinline__ uint32_t smem_u32(const void* p) {
    uint32_t a;
    asm("{ .reg .u64 t; cvta.to.shared.u64 t, %1; cvt.u32.u64 %0, t; }" : "=r"(a) : "l"(p));
    return a;
}
__device__ __forceinline__ void cpa16(uint32_t dst, const void* src) {
    asm volatile("cp.async.cg.shared.global [%0], [%1], 16;\n" :: "r"(dst), "l"(src));
}
#define CP_COMMIT()  asm volatile("cp.async.commit_group;\n")
#define CP_WAIT(n)   asm volatile("cp.async.wait_group %0;\n" :: "n"(n))

__device__ __forceinline__ void bulk_ld(uint32_t dst, const void* src, uint32_t bytes,
                                        uint32_t mbar) {
    asm volatile(
        "cp.async.bulk.shared::cluster.global.mbarrier::complete_tx::bytes [%0], [%1], %2, [%3];"
        :: "r"(dst), "l"(src), "r"(bytes), "r"(mbar) : "memory");
}
__device__ __forceinline__ void mbar_init(uint32_t m, uint32_t cnt) {
    asm volatile("mbarrier.init.shared.b64 [%0], %1;" :: "r"(m), "r"(cnt) : "memory");
}
__device__ __forceinline__ void mbar_expect(uint32_t m, uint32_t bytes) {
    asm volatile("mbarrier.arrive.expect_tx.shared.b64 _, [%0], %1;"
                 :: "r"(m), "r"(bytes) : "memory");
}
__device__ __forceinline__ void mbar_arrive(uint32_t m) {
    asm volatile("mbarrier.arrive.shared.b64 _, [%0];" :: "r"(m) : "memory");
}
__device__ __forceinline__ void mbar_wait(uint32_t m, uint32_t parity) {
    uint32_t done;
    asm volatile("{\n\t.reg .pred p;\n\t"
        "mbarrier.try_wait.parity.acquire.cta.shared::cta.b64 p, [%1], %2;\n\t"
        "selp.b32 %0, 1, 0, p;\n\t}"
        : "=r"(done) : "r"(m), "r"(parity) : "memory");
    if (!done) {
        asm volatile("{\n\t.reg .pred P1;\n\t"
            "WL_%=:\n\t"
            "mbarrier.try_wait.parity.acquire.cta.shared::cta.b64 P1, [%0], %1, 0x989680;\n\t"
            "@P1 bra.uni WD_%=;\n\t"
            "bra.uni WL_%=;\n\t"
            "WD_%=:\n\t}" :: "r"(m), "r"(parity) : "memory");
    }
}

#define LDSM4(r, a) \
    asm volatile("ldmatrix.sync.aligned.m8n8.x4.shared.b16 {%0,%1,%2,%3},[%4];" \
        : "=r"((r)[0]),"=r"((r)[1]),"=r"((r)[2]),"=r"((r)[3]) : "r"(a))
#define LDSM2(r, a) \
    asm volatile("ldmatrix.sync.aligned.m8n8.x2.shared.b16 {%0,%1},[%2];" \
        : "=r"((r)[0]),"=r"((r)[1]) : "r"(a))
#define MMA16816(d, a, b) \
    asm volatile("mma.sync.aligned.m16n8k16.row.col.f32.bf16.bf16.f32 " \
        "{%0,%1,%2,%3},{%4,%5,%6,%7},{%8,%9},{%0,%1,%2,%3};" \
        : "+f"((d)[0]),"+f"((d)[1]),"+f"((d)[2]),"+f"((d)[3]) \
        : "r"((a)[0]),"r"((a)[1]),"r"((a)[2]),"r"((a)[3]),"r"((b)[0]),"r"((b)[1]))

__device__ __forceinline__ float sigmoidf_(float x) { return 1.f / (1.f + expf(-x)); }

// ---------------- smem layout (bytes) ----------------
#define BS_OFF     0
#define MB_FULL    128
#define MB_EMPTY   192
#define MB_ZXF     256
#define WS_HI      1024
#define WS_STRIDE  1040
#define WS_LO      34304
#define RING_OFF   1024
#define A_BUF      16384
#define A_LOH      8192
#define ZP_OFF     132096
#define ZP_KG      9216
#define ZP_ROW     144
#define ZX_OFF     205824
#define SMEM_ZX    168960        // zx_gemm: ring + 4 zparts (R14 layout)
#define SMEM_MAIN  222208        // lstm_h: ring + 8 zparts + 2 zx slots

// ---------------- prologue kernels ----------------
__global__ void init_kernel() {
    int idx = blockIdx.x * blockDim.x + threadIdx.x;
    int stride = gridDim.x * blockDim.x;
    int* hh = (int*)g_hb_hi;
    int* hl = (int*)g_hb_lo;
    for (int i = idx; i < (2 * NCTA * 1024) / 4; i += stride) { hh[i] = 0; hl[i] = 0; }
    if (idx < NCTA) g_flags[idx] = 0u;
    if (idx < 2)    g_rel[idx]   = 0u;
}

__global__ void prep_w(const float* __restrict__ Wk, const float* __restrict__ Rk) {
    __shared__ float tile[32][33];
    int gt = blockIdx.x * 32, kt = blockIdx.y * 32;
    int tid = threadIdx.x;
    for (int i = tid; i < 1024; i += PTPB) {
        int kk = i >> 5, gg = i & 31;
        int k = kt + kk, g = gt + gg;
        tile[kk][gg] = (k < 512) ? Wk[(size_t)k * 2048 + g]
                                 : Rk[(size_t)(k - 512) * 2048 + g];
    }
    __syncthreads();
    for (int i = tid; i < 1024; i += PTPB) {
        int gg = i >> 5, kk = i & 31;
        float v = tile[kk][gg];
        __nv_bfloat16 hi = __float2bfloat16(v);
        __nv_bfloat16 lo = __float2bfloat16(v - __bfloat162float(hi));
        size_t o = (size_t)(gt + gg) * 1024 + (size_t)(kt + kk);
        g_w_hi[o] = hi; g_w_lo[o] = lo;
    }
}

__global__ void prep_x(const float* __restrict__ x) {
    int t = blockIdx.x, b = blockIdx.y;
    int bg = b >> 6, r = b & 63;
    const float* src = x + ((size_t)b * Tlen + t) * Isz;
    size_t tbase = (((size_t)t * 2 + bg) * 8) * 8192;
    for (int k = threadIdx.x; k < Isz; k += blockDim.x) {
        float v = src[k];
        __nv_bfloat16 hi = __float2bfloat16(v);
        __nv_bfloat16 lo = __float2bfloat16(v - __bfloat162float(hi));
        int kt = k >> 6, kk = k & 63;
        size_t off = tbase + (size_t)kt * 8192 + r * 128 + (((kk * 2) ^ ((r & 7) << 4)));
        *(__nv_bfloat16*)(g_xs_hi + off) = hi;
        *(__nv_bfloat16*)(g_xs_lo + off) = lo;
    }
}

// ---------------- prologue GEMM: z_x = x@W + bias (R14-proven, unchanged) ----------------
__global__ void __launch_bounds__(TPB, 1) zx_gemm(const float* __restrict__ bias) {
    extern __shared__ char smem[];
    const uint32_t sbase = smem_u32(smem);
    float* bs = (float*)(smem + BS_OFF);

    const int tid = threadIdx.x, wid = tid >> 5, lid = tid & 31;
    const int cta = blockIdx.x;
    const int cg  = cta & 63;
    const int bg  = cta >> 6;
    const int kg  = wid >> 1;
    const int ng  = wid & 1;

    for (int i = tid; i < 4096; i += TPB) {
        int half = i >= 2048;
        int j = half ? i - 2048 : i;
        int c = j >> 6, ch = j & 63;
        int g = (c & 3) * 512 + cg * 8 + (c >> 2);
        const __nv_bfloat16* src = (half ? g_w_lo : g_w_hi) + (size_t)g * 1024 + ch * 8;
        cpa16(sbase + (half ? WS_LO : WS_HI) + c * WS_STRIDE + ch * 16, src);
    }
    CP_COMMIT();
    if (tid < 32)
        bs[tid] = bias[(tid & 3) * 512 + cg * 8 + (tid >> 2)];
    if (tid == 0) {
        #pragma unroll
        for (int s = 0; s < NSTG; s++) {
            mbar_init(sbase + MB_FULL  + s * 8, 1);
            mbar_init(sbase + MB_EMPTY + s * 8, 2);
        }
    }
    CP_WAIT(0);
    __syncthreads();

    uint32_t Bh[2][4][2][2], Bl[2][4][2][2];
    if (wid < 8) {
        #pragma unroll
        for (int jj = 0; jj < 2; jj++) {
            const uint32_t koff = (kg + jj * 4) * 128;
            #pragma unroll
            for (int ks = 0; ks < 4; ks++)
                #pragma unroll
                for (int nt = 0; nt < 2; nt++) {
                    uint32_t a = sbase + WS_HI
                               + (ng * 16 + nt * 8 + (lid & 7)) * WS_STRIDE
                               + ((lid >> 3) & 1) * 16 + koff + ks * 32;
                    LDSM2(Bh[jj][ks][nt], a);
                    LDSM2(Bl[jj][ks][nt], a + (WS_LO - WS_HI));
                }
        }
    }
    __syncthreads();

    const int x_kt_p = (lid >> 1) + (lid & 1) * 4;

    if (wid == 8 && lid < 8) {
        const int s = lid;
        mbar_wait(sbase + MB_EMPTY + s * 8, 1);
        size_t o = (((size_t)0 * 2 + bg) * 8 + x_kt_p) * 8192;
        const uint32_t abuf = sbase + RING_OFF + s * A_BUF;
        mbar_expect(sbase + MB_FULL + s * 8, 16384);
        bulk_ld(abuf,         g_xs_hi + o, 8192, sbase + MB_FULL + s * 8);
        bulk_ld(abuf + A_LOH, g_xs_lo + o, 8192, sbase + MB_FULL + s * 8);
    }

    const uint32_t a_row   = (lid & 15) * 128;
    const uint32_t a_cmask = (lid & 7) << 4;
    const uint32_t a_chi   = (lid >> 4) * 16;

    for (int t = 0; t < Tlen; t++) {
        if (wid == 8) {
            if (lid < 8 && t + 1 < Tlen) {
                const int s = lid;
                mbar_wait(sbase + MB_EMPTY + s * 8, t & 1);
                size_t o = (((size_t)(t + 1) * 2 + bg) * 8 + x_kt_p) * 8192;
                const uint32_t abuf = sbase + RING_OFF + s * A_BUF;
                mbar_expect(sbase + MB_FULL + s * 8, 16384);
                bulk_ld(abuf,         g_xs_hi + o, 8192, sbase + MB_FULL + s * 8);
                bulk_ld(abuf + A_LOH, g_xs_lo + o, 8192, sbase + MB_FULL + s * 8);
            }
        } else {
            float acc[4][2][4];
            #pragma unroll
            for (int mt = 0; mt < 4; mt++)
                #pragma unroll
                for (int nt = 0; nt < 2; nt++)
                    #pragma unroll
                    for (int j = 0; j < 4; j++) acc[mt][nt][j] = 0.f;

            #pragma unroll
            for (int i = 0; i < 2; i++) {
                const int s = kg * 2 + i;
                mbar_wait(sbase + MB_FULL + s * 8, t & 1);
                const uint32_t abuf = sbase + RING_OFF + s * A_BUF;
                #pragma unroll
                for (int ks = 0; ks < 4; ks++) {
                    const uint32_t col = ((uint32_t)(ks * 32) + a_chi) ^ a_cmask;
                    #pragma unroll
                    for (int mt = 0; mt < 4; mt++) {
                        uint32_t ah[4], al[4];
                        LDSM4(ah, abuf + mt * 2048 + a_row + col);
                        LDSM4(al, abuf + A_LOH + mt * 2048 + a_row + col);
                        #pragma unroll
                        for (int nt = 0; nt < 2; nt++) {
                            MMA16816(acc[mt][nt], ah, Bh[i][ks][nt]);
                            MMA16816(acc[mt][nt], ah, Bl[i][ks][nt]);
                            MMA16816(acc[mt][nt], al, Bh[i][ks][nt]);
                        }
                    }
                }
                if (lid == 0) mbar_arrive(sbase + MB_EMPTY + s * 8);
            }

            #pragma unroll
            for (int mt = 0; mt < 4; mt++) {
                #pragma unroll
                for (int nt = 0; nt < 2; nt++) {
                    const int r0 = mt * 16 + (lid >> 2);
                    const int c0 = ng * 16 + nt * 8 + (lid & 3) * 2;
                    char* base = smem + ZP_OFF + kg * ZP_KG + c0 * 4;
                    *(float2*)(base + r0 * ZP_ROW) =
                        make_float2(acc[mt][nt][0], acc[mt][nt][1]);
                    *(float2*)(base + (r0 + 8) * ZP_ROW) =
                        make_float2(acc[mt][nt][2], acc[mt][nt][3]);
                }
            }
        }

        __syncthreads();

        if (wid < 8) {
            float4* dst = (float4*)(g_zx + ((size_t)t * NCTA + cta) * 8192);
            #pragma unroll
            for (int e = 0; e < 2; e++) {
                const int el = tid * 2 + e;
                const int hc = el & 7;
                float4 z = make_float4(0.f, 0.f, 0.f, 0.f);
                #pragma unroll
                for (int k4 = 0; k4 < 4; k4++) {
                    float4 p = *(const float4*)(smem + ZP_OFF + k4 * ZP_KG
                                                + (el >> 3) * ZP_ROW + hc * 16);
                    z.x += p.x; z.y += p.y; z.z += p.z; z.w += p.w;
                }
                z.x += bs[hc * 4 + 0];
                z.y += bs[hc * 4 + 1];
                z.z += bs[hc * 4 + 2];
                z.w += bs[hc * 4 + 3];
                dst[el] = z;
            }
        }

        __syncthreads();
    }
}

// ---------------- main recurrent kernel: z = z_x + h@R ----------------
// 8 compute warps = 8 kg (K=64 each, N=32 in regs), coalesced 8KB h gathers,
// per-bg hierarchical barrier.
__global__ void __launch_bounds__(TPB, 1) lstm_h(float* __restrict__ out) {
    extern __shared__ char smem[];
    const uint32_t sbase = smem_u32(smem);

    const int tid = threadIdx.x, wid = tid >> 5, lid = tid & 31;
    const int cta = blockIdx.x;
    const int cg  = cta & 63;
    const int bg  = cta >> 6;
    const int kg  = wid;             // wid<8: K-group = stage

    // weights (R part, k 512..1023) into smem
    for (int i = tid; i < 4096; i += TPB) {
        int half = i >= 2048;
        int j = half ? i - 2048 : i;
        int c = j >> 6, ch = j & 63;
        int g = (c & 3) * 512 + cg * 8 + (c >> 2);
        const __nv_bfloat16* src = (half ? g_w_lo : g_w_hi)
                                   + (size_t)g * 1024 + 512 + ch * 8;
        cpa16(sbase + (half ? WS_LO : WS_HI) + c * WS_STRIDE + ch * 16, src);
    }
    CP_COMMIT();
    if (tid == 0) {
        #pragma unroll
        for (int s = 0; s < NSTG; s++) {
            mbar_init(sbase + MB_FULL  + s * 8, 1);
            mbar_init(sbase + MB_EMPTY + s * 8, 1);
        }
        mbar_init(sbase + MB_ZXF,     1);
        mbar_init(sbase + MB_ZXF + 8, 1);
    }
    CP_WAIT(0);
    __syncthreads();

    // B fragments: warp kg owns k-slice [kg*64, +64), N=32 (4 nt tiles)
    uint32_t Bh[4][4][2], Bl[4][4][2];      // [ks][nt][2]
    if (wid < 8) {
        #pragma unroll
        for (int ks = 0; ks < 4; ks++)
            #pragma unroll
            for (int nt = 0; nt < 4; nt++) {
                uint32_t a = sbase + WS_HI
                           + (nt * 8 + (lid & 7)) * WS_STRIDE
                           + ((lid >> 3) & 1) * 16 + kg * 128 + ks * 32;
                LDSM2(Bh[ks][nt], a);
                LDSM2(Bl[ks][nt], a + (WS_LO - WS_HI));
            }
    }
    __syncthreads();   // ws dead; ring/zpart overlay

    // prime zx slots 0,1
    if (wid == 8 && lid == 30) {
        mbar_expect(sbase + MB_ZXF, 8192);
        bulk_ld(sbase + ZX_OFF, g_zx + ((size_t)0 * NCTA + cta) * 8192, 8192,
                sbase + MB_ZXF);
    }
    if (wid == 8 && lid == 31) {
        mbar_expect(sbase + MB_ZXF + 8, 8192);
        bulk_ld(sbase + ZX_OFF + 8192, g_zx + ((size_t)1 * NCTA + cta) * 8192, 8192,
                sbase + MB_ZXF + 8);
    }

    // A-fragment addressing (stage buf: [8 blocks][64 rows][16B], no swizzle)
    const uint32_t a_part = (uint32_t)((lid >> 4) * 1024 + (lid & 15) * 16);

    float creg[2] = {0.f, 0.f};

    for (int t = 0; t < Tlen; t++) {
        if (wid == 8) {
            // per-bg hierarchical barrier
            if (t > 0) {
                unsigned tt = (unsigned)t;
                if ((cta & 63) == 0) {
                    bool ok;
                    do {
                        ok = (g_flags[cta + lid]      >= tt)
                          && (g_flags[cta + 32 + lid] >= tt);
                    } while (!__all_sync(0xffffffffu, ok));
                    if (lid == 0) { __threadfence(); g_rel[bg] = tt; }
                } else if (lid == 0) {
                    while (g_rel[bg] < tt) { }
                }
                __syncwarp();
                __threadfence();
            }
            // coalesced gather: lane pair per stage, one 8KB load each
            if (lid < 16) {
                const int s = lid >> 1, half = lid & 1;
                const uint32_t fullb = sbase + MB_FULL  + s * 8;
                const uint32_t abuf  = sbase + RING_OFF + s * A_BUF;
                mbar_wait(sbase + MB_EMPTY + s * 8, (t + 1) & 1);
                const size_t src_off = ((size_t)(t & 1) * NCTA + bg * 64 + s * 8) * 1024;
                if (half == 0) {
                    mbar_expect(fullb, 16384);
                    bulk_ld(abuf, g_hb_hi + src_off, 8192, fullb);
                } else {
                    bulk_ld(abuf + A_LOH, g_hb_lo + src_off, 8192, fullb);
                }
            }
        } else {
            // compute warp kg: its one stage
            float acc[4][4][4];             // [mt][nt][4]
            #pragma unroll
            for (int mt = 0; mt < 4; mt++)
                #pragma unroll
                for (int nt = 0; nt < 4; nt++)
                    #pragma unroll
                    for (int j = 0; j < 4; j++) acc[mt][nt][j] = 0.f;

            mbar_wait(sbase + MB_FULL + kg * 8, t & 1);
            const uint32_t abuf = sbase + RING_OFF + kg * A_BUF;
            #pragma unroll
            for (int ks = 0; ks < 4; ks++) {
                #pragma unroll
                for (int mt = 0; mt < 4; mt++) {
                    uint32_t ah[4], al[4];
                    const uint32_t ao = abuf + ks * 2048 + mt * 256 + a_part;
                    LDSM4(ah, ao);
                    LDSM4(al, ao + A_LOH);
                    #pragma unroll
                    for (int nt = 0; nt < 4; nt++) {
                        MMA16816(acc[mt][nt], ah, Bh[ks][nt]);
                        MMA16816(acc[mt][nt], ah, Bl[ks][nt]);
                        MMA16816(acc[mt][nt], al, Bh[ks][nt]);
                    }
                }
            }
            if (lid == 0) mbar_arrive(sbase + MB_EMPTY + kg * 8);

            // fp32 partials -> zpart[kg]
            #pragma unroll
            for (int mt = 0; mt < 4; mt++) {
                #pragma unroll
                for (int nt = 0; nt < 4; nt++) {
                    const int r0 = mt * 16 + (lid >> 2);
                    const int c0 = nt * 8 + (lid & 3) * 2;
                    char* base = smem + ZP_OFF + kg * ZP_KG + c0 * 4;
                    *(float2*)(base + r0 * ZP_ROW) =
                        make_float2(acc[mt][nt][0], acc[mt][nt][1]);
                    *(float2*)(base + (r0 + 8) * ZP_ROW) =
                        make_float2(acc[mt][nt][2], acc[mt][nt][3]);
                }
            }
        }

        __syncthreads();    // partials visible

        if (wid < 8) {
            mbar_wait(sbase + MB_ZXF + (t & 1) * 8, (t >> 1) & 1);
            const int par2 = (t + 1) & 1;
            const int el0 = tid * 2;
            const int b   = el0 >> 3;
            const int hc0 = el0 & 7;
            float hv[2];
            #pragma unroll
            for (int e = 0; e < 2; e++) {
                const int el = el0 + e;
                const int hc = hc0 + e;
                float4 z = *(const float4*)(smem + ZX_OFF + (t & 1) * 8192 + el * 16);
                #pragma unroll
                for (int k8 = 0; k8 < 8; k8++) {
                    float4 p = *(const float4*)(smem + ZP_OFF + k8 * ZP_KG
                                                + b * ZP_ROW + hc * 16);
                    z.x += p.x; z.y += p.y; z.z += p.z; z.w += p.w;
                }
                float ii = sigmoidf_(z.x);
                float ff = sigmoidf_(z.y);
                float gg = tanhf(z.z);
                float oo = sigmoidf_(z.w);
                float cn = tanhf(ff * creg[e] + ii * gg);
                float hn = oo * cn;
                creg[e] = cn;
                hv[e] = hn;
                out[(size_t)(bg * 64 + b) * (Tlen * Hsz) + (size_t)t * Hsz
                    + cg * 8 + hc] = hn;
            }
            __nv_bfloat16 h0 = __float2bfloat16(hv[0]);
            __nv_bfloat16 h1 = __float2bfloat16(hv[1]);
            __nv_bfloat162 hi2; hi2.x = h0; hi2.y = h1;
            __nv_bfloat162 lo2;
            lo2.x = __float2bfloat16(hv[0] - __bfloat162float(h0));
            lo2.y = __float2bfloat16(hv[1] - __bfloat162float(h1));
            size_t boff = ((size_t)par2 * NCTA + cta) * 1024 + b * 16 + hc0 * 2;
            *(__nv_bfloat162*)(g_hb_hi + boff) = hi2;
            *(__nv_bfloat162*)(g_hb_lo + boff) = lo2;
            __threadfence();
        }

        __syncthreads();    // h published

        if (wid == 8) {
            if (lid == 0 && t < Tlen - 1)
                g_flags[cta] = (unsigned)(t + 1);
            if (lid == 31 && t + 2 < Tlen) {
                mbar_expect(sbase + MB_ZXF + (t & 1) * 8, 8192);
                bulk_ld(sbase + ZX_OFF + (t & 1) * 8192,
                        g_zx + ((size_t)(t + 2) * NCTA + cta) * 8192, 8192,
                        sbase + MB_ZXF + (t & 1) * 8);
            }
        }
    }
}

// ---------------- launch ----------------
extern "C" void kernel_launch(void* const* d_in, const int* in_sizes, int n_in,
                              void* d_out, int out_size) {
    const float* x    = (const float*)d_in[0];
    const float* Wk   = (const float*)d_in[1];
    const float* Rk   = (const float*)d_in[2];
    const float* bias = (const float*)d_in[3];
    float* out = (float*)d_out;

    cudaFuncSetAttribute(zx_gemm, cudaFuncAttributeMaxDynamicSharedMemorySize, SMEM_ZX);
    cudaFuncSetAttribute(lstm_h,  cudaFuncAttributeMaxDynamicSharedMemorySize, SMEM_MAIN);

    init_kernel<<<64, PTPB>>>();
    prep_w<<<dim3(64, 32), PTPB>>>(Wk, Rk);
    prep_x<<<dim3(Tlen, Bsz), 128>>>(x);
    zx_gemm<<<NCTA, TPB, SMEM_ZX>>>(bias);
    lstm_h<<<NCTA, TPB, SMEM_MAIN>>>(out);
}

// round 17
// speedup vs baseline: 2.2147x; 1.2563x over previous
#include <cuda_runtime.h>
#include <cuda_bf16.h>
#include <cstdint>

#define Bsz   128
#define Tlen  1024
#define Isz   512
#define Hsz   512
#define NCTA  128
#define TPB   288      // 8 compute warps (4 kg x 2 ng) + 1 producer warp
#define PTPB  256
#define NSTG  8

// ---------------- device scratch ----------------
__device__ __align__(1024) char g_xs_hi[(size_t)Tlen * 2 * 8 * 8192];  // swizzled x tiles
__device__ __align__(1024) char g_xs_lo[(size_t)Tlen * 2 * 8 * 8192];
__device__ __align__(1024) char g_hb_hi[2 * NCTA * 1024];              // [par][cta][64][8]bf16
__device__ __align__(1024) char g_hb_lo[2 * NCTA * 1024];
__device__ __nv_bfloat16 g_w_hi[(size_t)2048 * 1024];
__device__ __nv_bfloat16 g_w_lo[(size_t)2048 * 1024];
__device__ volatile unsigned g_flags[NCTA];
__device__ volatile unsigned g_rel[2];

// ---------------- helpers ----------------
__device__ __forceinline__ uint32_t smem_u32(const void* p) {
    uint32_t a;
    asm("{ .reg .u64 t; cvta.to.shared.u64 t, %1; cvt.u32.u64 %0, t; }" : "=r"(a) : "l"(p));
    return a;
}
__device__ __forceinline__ void cpa16(uint32_t dst, const void* src) {
    asm volatile("cp.async.cg.shared.global [%0], [%1], 16;\n" :: "r"(dst), "l"(src));
}
#define CP_COMMIT()  asm volatile("cp.async.commit_group;\n")
#define CP_WAIT(n)   asm volatile("cp.async.wait_group %0;\n" :: "n"(n))

__device__ __forceinline__ void bulk_ld(uint32_t dst, const void* src, uint32_t bytes,
                                        uint32_t mbar) {
    asm volatile(
        "cp.async.bulk.shared::cluster.global.mbarrier::complete_tx::bytes [%0], [%1], %2, [%3];"
        :: "r"(dst), "l"(src), "r"(bytes), "r"(mbar) : "memory");
}
__device__ __forceinline__ void mbar_init(uint32_t m, uint32_t cnt) {
    asm volatile("mbarrier.init.shared.b64 [%0], %1;" :: "r"(m), "r"(cnt) : "memory");
}
__device__ __forceinline__ void mbar_expect(uint32_t m, uint32_t bytes) {
    asm volatile("mbarrier.arrive.expect_tx.shared.b64 _, [%0], %1;"
                 :: "r"(m), "r"(bytes) : "memory");
}
__device__ __forceinline__ void mbar_arrive(uint32_t m) {
    asm volatile("mbarrier.arrive.shared.b64 _, [%0];" :: "r"(m) : "memory");
}
__device__ __forceinline__ void mbar_wait(uint32_t m, uint32_t parity) {
    uint32_t done;
    asm volatile("{\n\t.reg .pred p;\n\t"
        "mbarrier.try_wait.parity.acquire.cta.shared::cta.b64 p, [%1], %2;\n\t"
        "selp.b32 %0, 1, 0, p;\n\t}"
        : "=r"(done) : "r"(m), "r"(parity) : "memory");
    if (!done) {
        asm volatile("{\n\t.reg .pred P1;\n\t"
            "WL_%=:\n\t"
            "mbarrier.try_wait.parity.acquire.cta.shared::cta.b64 P1, [%0], %1, 0x989680;\n\t"
            "@P1 bra.uni WD_%=;\n\t"
            "bra.uni WL_%=;\n\t"
            "WD_%=:\n\t}" :: "r"(m), "r"(parity) : "memory");
    }
}

#define LDSM4(r, a) \
    asm volatile("ldmatrix.sync.aligned.m8n8.x4.shared.b16 {%0,%1,%2,%3},[%4];" \
        : "=r"((r)[0]),"=r"((r)[1]),"=r"((r)[2]),"=r"((r)[3]) : "r"(a))
#define LDSM2(r, a) \
    asm volatile("ldmatrix.sync.aligned.m8n8.x2.shared.b16 {%0,%1},[%2];" \
        : "=r"((r)[0]),"=r"((r)[1]) : "r"(a))
#define MMA16816(d, a, b) \
    asm volatile("mma.sync.aligned.m16n8k16.row.col.f32.bf16.bf16.f32 " \
        "{%0,%1,%2,%3},{%4,%5,%6,%7},{%8,%9},{%0,%1,%2,%3};" \
        : "+f"((d)[0]),"+f"((d)[1]),"+f"((d)[2]),"+f"((d)[3]) \
        : "r"((a)[0]),"r"((a)[1]),"r"((a)[2]),"r"((a)[3]),"r"((b)[0]),"r"((b)[1]))

__device__ __forceinline__ float sigmoidf_(float x) { return 1.f / (1.f + expf(-x)); }

// ---------------- smem layout (bytes) ----------------
// Phase 0: bias/mbars @0..1024, ws_hi @1024, ws_lo @67072 (ends 133120)
// Steady (overlays ws): ring 8x16384 @1024 (ends 132096),
//                       zpart 4x9216 @132096 (ends 168960)
#define BS_OFF     0
#define MB_FULL    128
#define MB_EMPTY   192
#define WS_HI      1024
#define WS_LO      67072
#define WS_STRIDE  2064
#define RING_OFF   1024
#define A_BUF      16384
#define A_LOH      8192
#define ZP_OFF     132096
#define ZP_KG      9216
#define ZP_ROW     144
#define SMEM_TOTAL 168960

// ---------------- prologue kernels ----------------
__global__ void init_kernel() {
    int idx = blockIdx.x * blockDim.x + threadIdx.x;
    int stride = gridDim.x * blockDim.x;
    int* hh = (int*)g_hb_hi;
    int* hl = (int*)g_hb_lo;
    for (int i = idx; i < (2 * NCTA * 1024) / 4; i += stride) { hh[i] = 0; hl[i] = 0; }
    if (idx < NCTA) g_flags[idx] = 0u;
    if (idx < 2)    g_rel[idx]   = 0u;
}

__global__ void prep_w(const float* __restrict__ Wk, const float* __restrict__ Rk) {
    __shared__ float tile[32][33];
    int gt = blockIdx.x * 32, kt = blockIdx.y * 32;
    int tid = threadIdx.x;
    for (int i = tid; i < 1024; i += PTPB) {
        int kk = i >> 5, gg = i & 31;
        int k = kt + kk, g = gt + gg;
        tile[kk][gg] = (k < 512) ? Wk[(size_t)k * 2048 + g]
                                 : Rk[(size_t)(k - 512) * 2048 + g];
    }
    __syncthreads();
    for (int i = tid; i < 1024; i += PTPB) {
        int gg = i >> 5, kk = i & 31;
        float v = tile[kk][gg];
        __nv_bfloat16 hi = __float2bfloat16(v);
        __nv_bfloat16 lo = __float2bfloat16(v - __bfloat162float(hi));
        size_t o = (size_t)(gt + gg) * 1024 + (size_t)(kt + kk);
        g_w_hi[o] = hi; g_w_lo[o] = lo;
    }
}

__global__ void prep_x(const float* __restrict__ x) {
    int t = blockIdx.x, b = blockIdx.y;
    int bg = b >> 6, r = b & 63;
    const float* src = x + ((size_t)b * Tlen + t) * Isz;
    size_t tbase = (((size_t)t * 2 + bg) * 8) * 8192;
    for (int k = threadIdx.x; k < Isz; k += blockDim.x) {
        float v = src[k];
        __nv_bfloat16 hi = __float2bfloat16(v);
        __nv_bfloat16 lo = __float2bfloat16(v - __bfloat162float(hi));
        int kt = k >> 6, kk = k & 63;
        size_t off = tbase + (size_t)kt * 8192 + r * 128 + (((kk * 2) ^ ((r & 7) << 4)));
        *(__nv_bfloat16*)(g_xs_hi + off) = hi;
        *(__nv_bfloat16*)(g_xs_lo + off) = lo;
    }
}

// ---------------- main persistent kernel ----------------
__global__ void __launch_bounds__(TPB, 1) lstm_mma(const float* __restrict__ bias,
                                                   float* __restrict__ out) {
    extern __shared__ char smem[];
    const uint32_t sbase = smem_u32(smem);
    float* bs = (float*)(smem + BS_OFF);

    const int tid = threadIdx.x, wid = tid >> 5, lid = tid & 31;
    const int cta = blockIdx.x;
    const int cg  = cta & 63;        // 8 h-cols
    const int bg  = cta >> 6;        // 64 batch rows
    const int kg  = wid >> 1;        // K-group: owns tiles kt = kg + 4i
    const int ng  = wid & 1;         // N-group (16 n-cols)

    // ---- phase 0: weights into smem (transient) ----
    for (int i = tid; i < 32 * 128 * 2; i += TPB) {
        int half = i >= 32 * 128;
        int j = half ? i - 32 * 128 : i;
        int c = j >> 7, ch = j & 127;
        int g = (c & 3) * 512 + cg * 8 + (c >> 2);
        const __nv_bfloat16* src = (half ? g_w_lo : g_w_hi) + (size_t)g * 1024 + ch * 8;
        cpa16(sbase + (half ? WS_LO : WS_HI) + c * WS_STRIDE + ch * 16, src);
    }
    CP_COMMIT();
    if (tid < 32)
        bs[tid] = bias[(tid & 3) * 512 + cg * 8 + (tid >> 2)];
    if (tid == 0) {
        #pragma unroll
        for (int s = 0; s < NSTG; s++) {
            mbar_init(sbase + MB_FULL  + s * 8, 1);
            mbar_init(sbase + MB_EMPTY + s * 8, 2);
        }
    }
    CP_WAIT(0);
    __syncthreads();

    // ---- extract B fragments (tiles kt = kg + 4i), held forever ----
    uint32_t Bh[16][2][2], Bl[16][2][2];
    if (wid < 8) {
        #pragma unroll
        for (int kc = 0; kc < 16; kc++) {           // kc = i*4 + ks
            const uint32_t koff = kg * 128 + (kc >> 2) * 512 + (kc & 3) * 32;
            #pragma unroll
            for (int nt = 0; nt < 2; nt++) {
                uint32_t a = sbase + WS_HI
                           + (ng * 16 + nt * 8 + (lid & 7)) * WS_STRIDE
                           + ((lid >> 3) & 1) * 16 + koff;
                LDSM2(Bh[kc][nt], a);
                LDSM2(Bl[kc][nt], a + (WS_LO - WS_HI));
            }
        }
    }
    __syncthreads();   // ws dead; ring/zpart overlay it

    // stage map: stage s serves x tile ktx(s) = (s>>1)+(s&1)*4 and h tile ktx+8
    const int x_kt = (lid >> 1) + (lid & 1) * 4;           // producer lane (lid<8)

    // ---- prime: lane s loads its x tile of step 0 (fresh-pass) ----
    if (wid == 8 && lid < 8) {
        const int s = lid;
        mbar_wait(sbase + MB_EMPTY + s * 8, 1);
        size_t o = (((size_t)0 * 2 + bg) * 8 + x_kt) * 8192;
        const uint32_t abuf = sbase + RING_OFF + s * A_BUF;
        mbar_expect(sbase + MB_FULL + s * 8, 16384);
        bulk_ld(abuf,         g_xs_hi + o, 8192, sbase + MB_FULL + s * 8);
        bulk_ld(abuf + A_LOH, g_xs_lo + o, 8192, sbase + MB_FULL + s * 8);
    }

    // compute A addressing: x tiles (swizzled rows of 128B)
    const uint32_t a_row   = (lid & 15) * 128;
    const uint32_t a_cmask = (lid & 7) << 4;
    const uint32_t a_chi   = (lid >> 4) * 16;
    // h tiles (block layout [8 blocks][64 rows][16B], R15-proven)
    const uint32_t a_part  = (uint32_t)((lid >> 4) * 1024 + (lid & 15) * 16);

    float creg[2] = {0.f, 0.f};

    for (int t = 0; t < Tlen; t++) {
        if (wid == 8) {
            // ---- per-bg hierarchical barrier ----
            if (t > 0) {
                unsigned tt = (unsigned)t;
                if ((cta & 63) == 0) {
                    bool ok;
                    do {
                        ok = (g_flags[cta + lid]      >= tt)
                          && (g_flags[cta + 32 + lid] >= tt);
                    } while (!__all_sync(0xffffffffu, ok));
                    if (lid == 0) { __threadfence(); g_rel[bg] = tt; }
                } else if (lid == 0) {
                    while (g_rel[bg] < tt) { }
                }
                __syncwarp();
                __threadfence();
            }
            // ---- 8 parallel lanes: h gather (coalesced 8KB) then x(t+1) ----
            if (lid < 8) {
                const int s = lid;
                const uint32_t abuf  = sbase + RING_OFF + s * A_BUF;
                const uint32_t fullb = sbase + MB_FULL  + s * 8;
                const uint32_t empb  = sbase + MB_EMPTY + s * 8;
                mbar_wait(empb, 0);              // x of step t consumed
                {
                    const size_t src_off =
                        ((size_t)(t & 1) * NCTA + bg * 64 + x_kt * 8) * 1024;
                    mbar_expect(fullb, 16384);
                    bulk_ld(abuf,         g_hb_hi + src_off, 8192, fullb);
                    bulk_ld(abuf + A_LOH, g_hb_lo + src_off, 8192, fullb);
                }
                if (t + 1 < Tlen) {
                    mbar_wait(empb, 1);          // h of step t consumed
                    size_t o = (((size_t)(t + 1) * 2 + bg) * 8 + x_kt) * 8192;
                    mbar_expect(fullb, 16384);
                    bulk_ld(abuf,         g_xs_hi + o, 8192, fullb);
                    bulk_ld(abuf + A_LOH, g_xs_lo + o, 8192, fullb);
                }
            }
        } else {
            // ---- compute warps: tiles kt = kg + 4i (i 0,1 = x; 2,3 = h) ----
            float acc[4][2][4];
            #pragma unroll
            for (int mt = 0; mt < 4; mt++)
                #pragma unroll
                for (int nt = 0; nt < 2; nt++)
                    #pragma unroll
                    for (int j = 0; j < 4; j++) acc[mt][nt][j] = 0.f;

            #pragma unroll
            for (int i = 0; i < 4; i++) {
                const int s = (kg << 1) | (i & 1);
                mbar_wait(sbase + MB_FULL + s * 8, i >> 1);   // x:0, h:1

                const uint32_t abuf = sbase + RING_OFF + s * A_BUF;
                if (i < 2) {
                    // swizzled x tile
                    #pragma unroll
                    for (int ks = 0; ks < 4; ks++) {
                        const uint32_t col = ((uint32_t)(ks * 32) + a_chi) ^ a_cmask;
                        #pragma unroll
                        for (int mt = 0; mt < 4; mt++) {
                            uint32_t ah[4], al[4];
                            LDSM4(ah, abuf + mt * 2048 + a_row + col);
                            LDSM4(al, abuf + A_LOH + mt * 2048 + a_row + col);
                            #pragma unroll
                            for (int nt = 0; nt < 2; nt++) {
                                MMA16816(acc[mt][nt], ah, Bh[i * 4 + ks][nt]);
                                MMA16816(acc[mt][nt], ah, Bl[i * 4 + ks][nt]);
                                MMA16816(acc[mt][nt], al, Bh[i * 4 + ks][nt]);
                            }
                        }
                    }
                } else {
                    // block-layout h tile
                    #pragma unroll
                    for (int ks = 0; ks < 4; ks++) {
                        #pragma unroll
                        for (int mt = 0; mt < 4; mt++) {
                            uint32_t ah[4], al[4];
                            const uint32_t ao = abuf + ks * 2048 + mt * 256 + a_part;
                            LDSM4(ah, ao);
                            LDSM4(al, ao + A_LOH);
                            #pragma unroll
                            for (int nt = 0; nt < 2; nt++) {
                                MMA16816(acc[mt][nt], ah, Bh[i * 4 + ks][nt]);
                                MMA16816(acc[mt][nt], ah, Bl[i * 4 + ks][nt]);
                                MMA16816(acc[mt][nt], al, Bh[i * 4 + ks][nt]);
                            }
                        }
                    }
                }
                if (lid == 0) mbar_arrive(sbase + MB_EMPTY + s * 8);
            }

            // fp32 partials -> zpart[kg]
            #pragma unroll
            for (int mt = 0; mt < 4; mt++) {
                #pragma unroll
                for (int nt = 0; nt < 2; nt++) {
                    const int r0 = mt * 16 + (lid >> 2);
                    const int c0 = ng * 16 + nt * 8 + (lid & 3) * 2;
                    char* base = smem + ZP_OFF + kg * ZP_KG + c0 * 4;
                    *(float2*)(base + r0 * ZP_ROW) =
                        make_float2(acc[mt][nt][0], acc[mt][nt][1]);
                    *(float2*)(base + (r0 + 8) * ZP_ROW) =
                        make_float2(acc[mt][nt][2], acc[mt][nt][3]);
                }
            }
        }

        __syncthreads();    // partials visible

        // ---- reduce + gates (compute threads, 2 adjacent h-cols each) ----
        if (wid < 8) {
            const int par2 = (t + 1) & 1;
            const int el0 = tid * 2;
            const int b   = el0 >> 3;
            const int hc0 = el0 & 7;
            float hv[2];
            #pragma unroll
            for (int e = 0; e < 2; e++) {
                const int hc = hc0 + e;
                float4 z = make_float4(0.f, 0.f, 0.f, 0.f);
                #pragma unroll
                for (int k4 = 0; k4 < 4; k4++) {
                    float4 p = *(const float4*)(smem + ZP_OFF + k4 * ZP_KG
                                                + b * ZP_ROW + hc * 16);
                    z.x += p.x; z.y += p.y; z.z += p.z; z.w += p.w;
                }
                float zi = z.x + bs[hc * 4 + 0];
                float zf = z.y + bs[hc * 4 + 1];
                float zg = z.z + bs[hc * 4 + 2];
                float zo = z.w + bs[hc * 4 + 3];
                float ii = sigmoidf_(zi);
                float ff = sigmoidf_(zf);
                float gg = tanhf(zg);
                float oo = sigmoidf_(zo);
                float cn = tanhf(ff * creg[e] + ii * gg);
                float hn = oo * cn;
                creg[e] = cn;
                hv[e] = hn;
                out[(size_t)(bg * 64 + b) * (Tlen * Hsz) + (size_t)t * Hsz
                    + cg * 8 + hc] = hn;
            }
            // coalesced h block store
            __nv_bfloat16 h0 = __float2bfloat16(hv[0]);
            __nv_bfloat16 h1 = __float2bfloat16(hv[1]);
            __nv_bfloat162 hi2; hi2.x = h0; hi2.y = h1;
            __nv_bfloat162 lo2;
            lo2.x = __float2bfloat16(hv[0] - __bfloat162float(h0));
            lo2.y = __float2bfloat16(hv[1] - __bfloat162float(h1));
            size_t boff = ((size_t)par2 * NCTA + cta) * 1024 + b * 16 + hc0 * 2;
            *(__nv_bfloat162*)(g_hb_hi + boff) = hi2;
            *(__nv_bfloat162*)(g_hb_lo + boff) = lo2;
            __threadfence();
        }

        __syncthreads();    // h published

        if (wid == 8 && lid == 0 && t < Tlen - 1)
            g_flags[cta] = (unsigned)(t + 1);
    }
}

// ---------------- launch ----------------
extern "C" void kernel_launch(void* const* d_in, const int* in_sizes, int n_in,
                              void* d_out, int out_size) {
    const float* x    = (const float*)d_in[0];
    const float* Wk   = (const float*)d_in[1];
    const float* Rk   = (const float*)d_in[2];
    const float* bias = (const float*)d_in[3];
    float* out = (float*)d_out;

    cudaFuncSetAttribute(lstm_mma, cudaFuncAttributeMaxDynamicSharedMemorySize, SMEM_TOTAL);

    init_kernel<<<64, PTPB>>>();
    prep_w<<<dim3(64, 32), PTPB>>>(Wk, Rk);
    prep_x<<<dim3(Tlen, Bsz), 128>>>(x);
    lstm_mma<<<NCTA, TPB, SMEM_TOTAL>>>(bias, out);
}